// round 11
// baseline (speedup 1.0000x reference)
#include <cuda_runtime.h>

#define Bb 512
#define Nn 10020
#define Ll 20
#define Ss 10
#define Hh 1001
#define HL 20020            // Hh * Ll
#define INV_SQRT6 0.40824829046386296f

// Output partition offsets (floats) in d_out, concat order:
// reconstructed, P, p1, p2, st, rot_axes, nw, contribution
#define O_REC 0
#define O_P   15390720
#define O_P1  16928256
#define O_P2  18465792
#define O_ST  20003328
#define O_ROT 50754048
#define O_NW  81504768
#define O_CB  91534788

// precompute tables
__device__ float4 g_t0[HL];   // (cos, sin, nw_g, scaling)
__device__ float4 g_t1[HL];   // (Wd0, Wd1, Wd2, 0)
__device__ float  g_rowsum[Nn];

// ---------------------------------------------------------------------------
// Kernel 0: per-(h,l) constant tables + rowsum table
// ---------------------------------------------------------------------------
__global__ void k_tables(const float* __restrict__ angles,
                         const float* __restrict__ W_enc,
                         const float* __restrict__ W_dec,
                         const float* __restrict__ scaling)
{
    int idx = blockIdx.x * blockDim.x + threadIdx.x;
    if (idx < HL) {
        int h = idx / Ll, l = idx % Ll;
        int n = Ss * h + l;                 // atom index
        int ha = n / Ss, l0 = n % Ss;
        float rs = 0.f;
        if (ha < Hh) rs += W_enc[(l0 * Hh + ha) * 3];
        if (ha >= 1) rs += W_enc[((l0 + Ss) * Hh + (ha - 1)) * 3];
        float a = angles[idx];
        float4 t0;
        t0.x = cosf(a);
        t0.y = sinf(a);
        t0.z = W_enc[(l * Hh + h) * 3] / rs;
        t0.w = scaling[n];
        g_t0[idx] = t0;
        float4 t1;
        t1.x = W_dec[(0 * Hh + h) * Ll + l];
        t1.y = W_dec[(1 * Hh + h) * Ll + l];
        t1.z = W_dec[(2 * Hh + h) * Ll + l];
        t1.w = 0.f;
        g_t1[idx] = t1;
    }
    if (idx < Nn) {
        int n = idx;
        int ha = n / Ss;
        float rs = 0.f;
        if (ha < Hh) rs += W_enc[((n % Ss) * Hh + ha) * 3];
        if (ha >= 1) rs += W_enc[((n % Ss + Ss) * Hh + ha - 1) * 3];
        g_rowsum[n] = rs;
    }
}

// ---------------------------------------------------------------------------
// Frame = (P, p1, p2, p12) for one (b, h)
// ---------------------------------------------------------------------------
struct Frame {
    float Px, Py, Pz, p1x, p1y, p1z, p2x, p2y, p2z, cx, cy, cz;
};

__device__ __forceinline__ Frame compute_frame(const float* __restrict__ W_enc,
                                               const float* __restrict__ sxp,
                                               int h)
{
    float e00=0,e01=0,e02=0, e10=0,e11=0,e12=0, e20=0,e21=0,e22=0;
#pragma unroll
    for (int i = 0; i < Ll; i++) {
        const float* w = &W_enc[(i * Hh + h) * 3];
        float w0 = w[0], w1 = w[1], w2 = w[2];
        float x0 = sxp[3*i + 0];
        float x1 = sxp[3*i + 1];
        float x2 = sxp[3*i + 2];
        e00 += x0 * w0; e01 += x1 * w0; e02 += x2 * w0;
        e10 += x0 * w1; e11 += x1 * w1; e12 += x2 * w1;
        e20 += x0 * w2; e21 += x1 * w2; e22 += x2 * w2;
    }
    Frame F;
    F.Px = e00; F.Py = e01; F.Pz = e02;
    float d1x = e10 - F.Px, d1y = e11 - F.Py, d1z = e12 - F.Pz;
    float d2x = e20 - F.Px, d2y = e21 - F.Py, d2z = e22 - F.Pz;
    float n1 = sqrtf(d1x*d1x + d1y*d1y + d1z*d1z); if (n1 == 0.f) n1 = 1.f;
    float n2 = sqrtf(d2x*d2x + d2y*d2y + d2z*d2z); if (n2 == 0.f) n2 = 1.f;
    float i1 = 1.f / n1, i2 = 1.f / n2;
    F.p1x = d1x*i1; F.p1y = d1y*i1; F.p1z = d1z*i1;
    F.p2x = d2x*i2; F.p2y = d2y*i2; F.p2z = d2z*i2;
    F.cx = (F.p1y*F.p2z - F.p1z*F.p2y) * INV_SQRT6;
    F.cy = (F.p1z*F.p2x - F.p1x*F.p2z) * INV_SQRT6;
    F.cz = (F.p1x*F.p2y - F.p1y*F.p2x) * INV_SQRT6;
    return F;
}

// rec contribution of table entry hl given frame F
__device__ __forceinline__ void rec_contrib(int hl, const Frame& F,
                                            float& a0, float& a1, float& a2)
{
    float4 t1 = g_t1[hl];
    float rxa = F.p1x * t1.x + F.p2x * t1.y + F.cx * t1.z;
    float rya = F.p1y * t1.x + F.p2y * t1.y + F.cy * t1.z;
    float rza = F.p1z * t1.x + F.p2z * t1.y + F.cz * t1.z;
    float4 t0 = g_t0[hl];
    float qw = t0.x, s = t0.y, nwg = t0.z, sc = t0.w;
    float qx = s * rxa, qy = s * rya, qz = s * rza;
    float tw = -qx*F.p1x - qy*F.p1y - qz*F.p1z;
    float tx =  qw*F.p1x + qy*F.p1z - qz*F.p1y;
    float ty =  qw*F.p1y + qz*F.p1x - qx*F.p1z;
    float tz =  qw*F.p1z + qx*F.p1y - qy*F.p1x;
    float vx = -tw*qx + tx*qw - ty*qz + tz*qy;
    float vy = -tw*qy + ty*qw - tz*qx + tx*qz;
    float vz = -tw*qz + tz*qw - tx*qy + ty*qx;
    a0 += (sc * vx + F.Px) * nwg;
    a1 += (sc * vy + F.Py) * nwg;
    a2 += (sc * vz + F.Pz) * nwg;
}

// ---------------------------------------------------------------------------
// Fused kernel. Block = 128 consecutive h, grid = (8, B).
// rec is a GATHER now: thread tid exclusively owns positions
// [base+10*tid, base+10*tid+10), contributions (h, l=j) + (h-1, l=j+10);
// neighbor frames come from SMEM (ghost h0-1 computed by tid 0).
// No register-resident rec array -> no spills.
// ---------------------------------------------------------------------------
#define HBLK 128
#define NPOS 1280
#define SXPOS (NPOS + Ll)                 // 1300 positions: [base-10, base+1290)
#define SXF   (SXPOS * 3)                 // 3900 floats
#define BUFF  (HBLK * 60)                 // 7680 floats (rot staging / rec acc)
#define ACCF  (NPOS * 3)                  // 3840 floats

__global__ __launch_bounds__(HBLK) void k_encode(const float* __restrict__ x,
                                                 const float* __restrict__ W_enc,
                                                 float* __restrict__ out)
{
    __shared__ __align__(16) float sx [SXF];
    __shared__ __align__(16) float buf[BUFF];
    __shared__ float pvals[(HBLK + 1) * 12];   // slot 0 = ghost, slot tid+1 = h

    const int b    = blockIdx.y;
    const int h0   = blockIdx.x * HBLK;
    const int tid  = threadIdx.x;
    const int base = Ss * h0;

    // stage x window [base-10, base+1290)
    const int xb = b * Nn * 3 + (base - Ss) * 3;
    for (int i = tid; i < SXF; i += HBLK) {
        int pos = base - Ss + i / 3;
        sx[i] = (pos >= 0 && pos < Nn) ? x[xb + i] : 0.f;
    }
    __syncthreads();

    const int h = h0 + tid;
    const bool active = (h < Hh);
    const int m = (Hh - h0 < HBLK) ? (Hh - h0) : HBLK;   // active h count

    Frame F;
    if (active) {
        F = compute_frame(W_enc, sx + 30 * tid + 30, h);
        float* pv = &pvals[(tid + 1) * 12];
        pv[0] = F.Px;  pv[1] = F.Py;  pv[2] = F.Pz;
        pv[3] = F.p1x; pv[4] = F.p1y; pv[5] = F.p1z;
        pv[6] = F.p2x; pv[7] = F.p2y; pv[8] = F.p2z;
        pv[9] = F.cx;  pv[10] = F.cy; pv[11] = F.cz;

        // rot_axes -> SMEM staging
#pragma unroll
        for (int l = 0; l < Ll; l++) {
            float4 t1 = g_t1[h * Ll + l];
            buf[60*tid + 3*l + 0] = F.p1x * t1.x + F.p2x * t1.y + F.cx * t1.z;
            buf[60*tid + 3*l + 1] = F.p1y * t1.x + F.p2y * t1.y + F.cy * t1.z;
            buf[60*tid + 3*l + 2] = F.p1z * t1.x + F.p2z * t1.y + F.cz * t1.z;
        }
    }
    if (tid == 0 && h0 > 0) {
        Frame G = compute_frame(W_enc, sx, h0 - 1);
        pvals[0] = G.Px;  pvals[1] = G.Py;  pvals[2] = G.Pz;
        pvals[3] = G.p1x; pvals[4] = G.p1y; pvals[5] = G.p1z;
        pvals[6] = G.p2x; pvals[7] = G.p2y; pvals[8] = G.p2z;
        pvals[9] = G.cx;  pvals[10] = G.cy; pvals[11] = G.cz;
    }
    __syncthreads();

    // rot writeout: coalesced float4 from staging
    {
        const int rb = O_ROT + (b * Hh + h0) * 60;       // mod 4 == 0
        const int nv = (60 * m) >> 2;
        const float4* src = (const float4*)buf;
        float4* dst = (float4*)(out + rb);
        for (int v = tid; v < nv; v += HBLK) dst[v] = src[v];
    }

    // P/p1/p2 writeout: coalesced from pvals. region r: component base 3r.
#pragma unroll
    for (int rgn = 0; rgn < 3; rgn++) {
        const int ob = (rgn == 0 ? O_P : (rgn == 1 ? O_P1 : O_P2))
                     + (b * Hh + h0) * 3;
        const int c0 = 3 * rgn;
        const int rowf = 3 * m;
        const int head = (4 - (ob & 3)) & 3;
        for (int f = tid; f < head; f += HBLK) {
            int dh = f / 3;
            out[ob + f] = pvals[(dh + 1) * 12 + c0 + (f - 3 * dh)];
        }
        const int nv = (rowf - head) >> 2;
        for (int v = tid; v < nv; v += HBLK) {
            int f0 = head + 4 * v;
            float4 q;
            int d0=(f0+0)/3, d1=(f0+1)/3, d2=(f0+2)/3, d3=(f0+3)/3;
            q.x = pvals[(d0+1)*12 + c0 + (f0+0) - 3*d0];
            q.y = pvals[(d1+1)*12 + c0 + (f0+1) - 3*d1];
            q.z = pvals[(d2+1)*12 + c0 + (f0+2) - 3*d2];
            q.w = pvals[(d3+1)*12 + c0 + (f0+3) - 3*d3];
            *(float4*)(out + ob + f0) = q;
        }
        for (int f = head + 4 * nv + tid; f < rowf; f += HBLK) {
            int dh = f / 3;
            out[ob + f] = pvals[(dh + 1) * 12 + c0 + (f - 3 * dh)];
        }
    }

    // st writeout: float4 reshuffle of sx. st[b,i,h,k] = x[b, 10h+i, k]
    for (int i = 0; i < Ll; i++) {
        const int rb = O_ST + (b * Ll + i) * (Hh * 3) + h0 * 3;
        const int rowf = 3 * m;
        const int head = (4 - (rb & 3)) & 3;
        for (int f = tid; f < head; f += HBLK) {
            int dh = f / 3, k = f - 3 * dh;
            out[rb + f] = sx[30 * dh + 30 + 3*i + k];
        }
        const int nv = (rowf - head) >> 2;
        for (int v = tid; v < nv; v += HBLK) {
            int f0 = head + 4 * v;
            float4 q;
            int d0=(f0+0)/3, d1=(f0+1)/3, d2=(f0+2)/3, d3=(f0+3)/3;
            q.x = sx[30*d0 + 30 + 3*i + (f0+0) - 3*d0];
            q.y = sx[30*d1 + 30 + 3*i + (f0+1) - 3*d1];
            q.z = sx[30*d2 + 30 + 3*i + (f0+2) - 3*d2];
            q.w = sx[30*d3 + 30 + 3*i + (f0+3) - 3*d3];
            *(float4*)(out + rb + f0) = q;
        }
        for (int f = head + 4*nv + tid; f < rowf; f += HBLK) {
            int dh = f / 3, k = f - 3 * dh;
            out[rb + f] = sx[30 * dh + 30 + 3*i + k];
        }
    }
    __syncthreads();

    // rec GATHER into buf[0..30*nown): thread tid owns n in [base+10*tid, +10)
    const bool own_any = (base + Ss * tid < Nn);
    if (own_any) {
        const bool nb_valid = (tid == 0) ? (h0 > 0) : (h0 + tid - 1 < Hh);
        Frame Nb;
        if (nb_valid) {
            const float* pv = &pvals[tid * 12];
            Nb.Px  = pv[0];  Nb.Py  = pv[1];  Nb.Pz  = pv[2];
            Nb.p1x = pv[3];  Nb.p1y = pv[4];  Nb.p1z = pv[5];
            Nb.p2x = pv[6];  Nb.p2y = pv[7];  Nb.p2z = pv[8];
            Nb.cx  = pv[9];  Nb.cy  = pv[10]; Nb.cz  = pv[11];
        }
#pragma unroll
        for (int j = 0; j < Ss; j++) {
            float a0 = 0.f, a1 = 0.f, a2 = 0.f;
            if (active)   rec_contrib(h * Ll + j, F, a0, a1, a2);
            if (nb_valid) rec_contrib((h - 1) * Ll + j + Ss, Nb, a0, a1, a2);
            buf[30 * tid + 3*j + 0] = a0;
            buf[30 * tid + 3*j + 1] = a1;
            buf[30 * tid + 3*j + 2] = a2;
        }
    }
    __syncthreads();

    // rec writeback: coalesced float4 plain stores (exclusive ownership)
    {
        const int gb = (b * Nn + base) * 3;              // O_REC == 0, mod 4 == 0
        int maxf = (Nn - base) * 3;
        if (maxf > ACCF) maxf = ACCF;
        const int nv = maxf >> 2;                        // divisible by 4
        const float4* src = (const float4*)buf;
        float4* dst = (float4*)(out + gb);
        for (int v = tid; v < nv; v += HBLK) dst[v] = src[v];
    }
}

// ---------------------------------------------------------------------------
// k_nw: one block per n, vectorized float4 row writes for nw + contribution
// ---------------------------------------------------------------------------
__device__ __forceinline__ void nw_vals(int h, int ended, int started,
                                        int ha, float wA, float wB,
                                        float& cb, float& nw)
{
    cb = (h >= ended && h < started) ? 1.f : 0.f;
    nw = (h == ha) ? wA : ((h == ha - 1) ? wB : 0.f);
}

__global__ void k_nw(const float* __restrict__ W_enc,
                     float* __restrict__ out)
{
    const int n   = blockIdx.x;
    const int tid = threadIdx.x;
    const int bd  = blockDim.x;

    const int started = (n < Nn - Ll) ? (n / Ss + 1) : Hh;
    const int ended   = (n >= Ll) ? ((n - Ss) / Ss) : 0;
    const int ha = n / Ss, l0 = n % Ss;
    const float inv_rs = 1.f / g_rowsum[n];
    const float wA = (ha < Hh) ? W_enc[(l0 * Hh + ha) * 3] * inv_rs : 0.f;
    const float wB = (ha >= 1) ? W_enc[((l0 + Ss) * Hh + ha - 1) * 3] * inv_rs : 0.f;

    const int bn = O_NW + n * Hh;
    const int bc = O_CB + n * Hh;
    const int head = (4 - (n & 3)) & 3;           // bn,bc ≡ n (mod 4)

    for (int h = tid; h < head; h += bd) {
        float cb, nw; nw_vals(h, ended, started, ha, wA, wB, cb, nw);
        out[bn + h] = nw; out[bc + h] = cb;
    }
    const int nvec = (Hh - head) >> 2;
    float4* vn = (float4*)(out + bn + head);
    float4* vc = (float4*)(out + bc + head);
    for (int v = tid; v < nvec; v += bd) {
        int h = head + 4 * v;
        float4 c4, w4;
        nw_vals(h + 0, ended, started, ha, wA, wB, c4.x, w4.x);
        nw_vals(h + 1, ended, started, ha, wA, wB, c4.y, w4.y);
        nw_vals(h + 2, ended, started, ha, wA, wB, c4.z, w4.z);
        nw_vals(h + 3, ended, started, ha, wA, wB, c4.w, w4.w);
        vn[v] = w4; vc[v] = c4;
    }
    for (int h = head + 4 * nvec + tid; h < Hh; h += bd) {
        float cb, nw; nw_vals(h, ended, started, ha, wA, wB, cb, nw);
        out[bn + h] = nw; out[bc + h] = cb;
    }
}

// ---------------------------------------------------------------------------
extern "C" void kernel_launch(void* const* d_in, const int* in_sizes, int n_in,
                              void* d_out, int out_size)
{
    const float* x       = (const float*)d_in[0];
    const float* W_enc   = (const float*)d_in[1];
    const float* W_dec   = (const float*)d_in[2];
    const float* angles  = (const float*)d_in[3];
    const float* scaling = (const float*)d_in[4];
    float* out = (float*)d_out;

    k_tables<<<(HL + 255) / 256, 256>>>(angles, W_enc, W_dec, scaling);

    dim3 gA((Hh + HBLK - 1) / HBLK, Bb);
    k_encode<<<gA, HBLK>>>(x, W_enc, out);

    k_nw<<<Nn, 256>>>(W_enc, out);
}

// round 12
// speedup vs baseline: 2.0932x; 2.0932x over previous
#include <cuda_runtime.h>

#define Bb 512
#define Nn 10020
#define Ll 20
#define Ss 10
#define Hh 1001
#define HL 20020            // Hh * Ll
#define INV_SQRT6 0.40824829046386296f

// Output partition offsets (floats) in d_out, concat order:
// reconstructed, P, p1, p2, st, rot_axes, nw, contribution
#define O_REC 0
#define O_P   15390720
#define O_P1  16928256
#define O_P2  18465792
#define O_ST  20003328
#define O_ROT 50754048
#define O_NW  81504768
#define O_CB  91534788

// precompute tables, TRANSPOSED to [l][h] so hot-loop loads are coalesced
// across a warp of consecutive h.
__device__ float4 g_t0[HL];   // [l*Hh + h] = (cos, sin, nw_g, scaling)
__device__ float4 g_t1[HL];   // [l*Hh + h] = (Wd0, Wd1, Wd2, 0)
__device__ float  g_rowsum[Nn];

// ---------------------------------------------------------------------------
// Kernel 0: per-(h,l) constant tables (transposed layout) + rowsum table
// ---------------------------------------------------------------------------
__global__ void k_tables(const float* __restrict__ angles,
                         const float* __restrict__ W_enc,
                         const float* __restrict__ W_dec,
                         const float* __restrict__ scaling)
{
    int idx = blockIdx.x * blockDim.x + threadIdx.x;
    if (idx < HL) {
        int l = idx / Hh, h = idx % Hh;     // h fastest -> coalesced writes
        int ai = h * Ll + l;                // angle / scaling index
        int n = Ss * h + l;                 // atom index
        int ha = n / Ss, l0 = n % Ss;
        float rs = 0.f;
        if (ha < Hh) rs += W_enc[(l0 * Hh + ha) * 3];
        if (ha >= 1) rs += W_enc[((l0 + Ss) * Hh + (ha - 1)) * 3];
        float a = angles[ai];
        float4 t0;
        t0.x = cosf(a);
        t0.y = sinf(a);
        t0.z = W_enc[(l * Hh + h) * 3] / rs;
        t0.w = scaling[n];
        g_t0[idx] = t0;
        float4 t1;
        t1.x = W_dec[(0 * Hh + h) * Ll + l];
        t1.y = W_dec[(1 * Hh + h) * Ll + l];
        t1.z = W_dec[(2 * Hh + h) * Ll + l];
        t1.w = 0.f;
        g_t1[idx] = t1;
    }
    if (idx < Nn) {
        int n = idx;
        int ha = n / Ss;
        float rs = 0.f;
        if (ha < Hh) rs += W_enc[((n % Ss) * Hh + ha) * 3];
        if (ha >= 1) rs += W_enc[((n % Ss + Ss) * Hh + ha - 1) * 3];
        g_rowsum[n] = rs;
    }
}

// ---------------------------------------------------------------------------
// Fused kernel (R10 structure). Block = 128 consecutive h, grid = (8, B).
// Exclusively owns positions [base, base+1280): contributions from
// h in [h0-1 .. h0+127], where h0-1 is a "ghost" recomputed by tid 0.
// rot_axes staged in SMEM -> coalesced float4; st = float4 reshuffle of sx;
// reconstructed written with plain coalesced float4 (no memset, no atomics).
// ---------------------------------------------------------------------------
#define HBLK 128
#define NPOS 1280
#define SXPOS (NPOS + Ll)                 // 1300 positions: [base-10, base+1290)
#define SXF   (SXPOS * 3)                 // 3900 floats
#define BUFF  (HBLK * 60)                 // 7680 floats (rot staging / rec acc)
#define ACCF  (NPOS * 3)                  // 3840 floats

__global__ __launch_bounds__(HBLK) void k_encode(const float* __restrict__ x,
                                                 const float* __restrict__ W_enc,
                                                 float* __restrict__ out)
{
    __shared__ __align__(16) float sx [SXF];
    __shared__ __align__(16) float buf[BUFF];
    __shared__ float sg[30];

    const int b    = blockIdx.y;
    const int h0   = blockIdx.x * HBLK;
    const int tid  = threadIdx.x;
    const int base = Ss * h0;

    // stage x window [base-10, base+1290)
    const int xb = b * Nn * 3 + (base - Ss) * 3;
    for (int i = tid; i < SXF; i += HBLK) {
        int pos = base - Ss + i / 3;
        sx[i] = (pos >= 0 && pos < Nn) ? x[xb + i] : 0.f;
    }
    __syncthreads();

    const int h = h0 + tid;
    const bool active = (h < Hh);
    float r[60];

    if (active) {
        // emb[l][k] = sum_i x[b, 10h+i, k] * W_enc[i, h, l]
        float e00=0,e01=0,e02=0, e10=0,e11=0,e12=0, e20=0,e21=0,e22=0;
        const int lo = 30 * tid + 30;
#pragma unroll
        for (int i = 0; i < Ll; i++) {
            const float* w = &W_enc[(i * Hh + h) * 3];
            float w0 = w[0], w1 = w[1], w2 = w[2];
            float x0 = sx[lo + 3*i + 0];
            float x1 = sx[lo + 3*i + 1];
            float x2 = sx[lo + 3*i + 2];
            e00 += x0 * w0; e01 += x1 * w0; e02 += x2 * w0;
            e10 += x0 * w1; e11 += x1 * w1; e12 += x2 * w1;
            e20 += x0 * w2; e21 += x1 * w2; e22 += x2 * w2;
        }

        float Px = e00, Py = e01, Pz = e02;
        float d1x = e10 - Px, d1y = e11 - Py, d1z = e12 - Pz;
        float d2x = e20 - Px, d2y = e21 - Py, d2z = e22 - Pz;
        float n1 = sqrtf(d1x*d1x + d1y*d1y + d1z*d1z); if (n1 == 0.f) n1 = 1.f;
        float n2 = sqrtf(d2x*d2x + d2y*d2y + d2z*d2z); if (n2 == 0.f) n2 = 1.f;
        float i1 = 1.f / n1, i2 = 1.f / n2;
        float p1x = d1x*i1, p1y = d1y*i1, p1z = d1z*i1;
        float p2x = d2x*i2, p2y = d2y*i2, p2z = d2z*i2;
        float cx = (p1y*p2z - p1z*p2y) * INV_SQRT6;
        float cy = (p1z*p2x - p1x*p2z) * INV_SQRT6;
        float cz = (p1x*p2y - p1y*p2x) * INV_SQRT6;

        int pb = (b * Hh + h) * 3;
        out[O_P  + pb + 0] = Px;  out[O_P  + pb + 1] = Py;  out[O_P  + pb + 2] = Pz;
        out[O_P1 + pb + 0] = p1x; out[O_P1 + pb + 1] = p1y; out[O_P1 + pb + 2] = p1z;
        out[O_P2 + pb + 0] = p2x; out[O_P2 + pb + 1] = p2y; out[O_P2 + pb + 2] = p2z;

        // rot_axes -> SMEM staging; rec contributions -> registers
        // table loads are coalesced: g_tX[l*Hh + h], consecutive h per warp
#pragma unroll
        for (int l = 0; l < Ll; l++) {
            float4 t1 = g_t1[l * Hh + h];
            float rxa = p1x * t1.x + p2x * t1.y + cx * t1.z;
            float rya = p1y * t1.x + p2y * t1.y + cy * t1.z;
            float rza = p1z * t1.x + p2z * t1.y + cz * t1.z;
            buf[60 * tid + 3*l + 0] = rxa;
            buf[60 * tid + 3*l + 1] = rya;
            buf[60 * tid + 3*l + 2] = rza;

            float4 t0 = g_t0[l * Hh + h];
            float qw = t0.x, s = t0.y, nwg = t0.z, sc = t0.w;
            float qx = s * rxa, qy = s * rya, qz = s * rza;
            float tw = -qx*p1x - qy*p1y - qz*p1z;
            float tx =  qw*p1x + qy*p1z - qz*p1y;
            float ty =  qw*p1y + qz*p1x - qx*p1z;
            float tz =  qw*p1z + qx*p1y - qy*p1x;
            float vx = -tw*qx + tx*qw - ty*qz + tz*qy;
            float vy = -tw*qy + ty*qw - tz*qx + tx*qz;
            float vz = -tw*qz + tz*qw - tx*qy + ty*qx;
            r[3*l + 0] = (sc * vx + Px) * nwg;
            r[3*l + 1] = (sc * vy + Py) * nwg;
            r[3*l + 2] = (sc * vz + Pz) * nwg;
        }
    }

    // ghost h0-1 (tid 0): rec contributions for l=10..19 into sg
    if (tid == 0 && h0 > 0) {
        const int hg = h0 - 1;
        float e00=0,e01=0,e02=0, e10=0,e11=0,e12=0, e20=0,e21=0,e22=0;
#pragma unroll
        for (int i = 0; i < Ll; i++) {
            const float* w = &W_enc[(i * Hh + hg) * 3];
            float w0 = w[0], w1 = w[1], w2 = w[2];
            float x0 = sx[3*i + 0];
            float x1 = sx[3*i + 1];
            float x2 = sx[3*i + 2];
            e00 += x0 * w0; e01 += x1 * w0; e02 += x2 * w0;
            e10 += x0 * w1; e11 += x1 * w1; e12 += x2 * w1;
            e20 += x0 * w2; e21 += x1 * w2; e22 += x2 * w2;
        }
        float Px = e00, Py = e01, Pz = e02;
        float d1x = e10 - Px, d1y = e11 - Py, d1z = e12 - Pz;
        float d2x = e20 - Px, d2y = e21 - Py, d2z = e22 - Pz;
        float n1 = sqrtf(d1x*d1x + d1y*d1y + d1z*d1z); if (n1 == 0.f) n1 = 1.f;
        float n2 = sqrtf(d2x*d2x + d2y*d2y + d2z*d2z); if (n2 == 0.f) n2 = 1.f;
        float i1 = 1.f / n1, i2 = 1.f / n2;
        float p1x = d1x*i1, p1y = d1y*i1, p1z = d1z*i1;
        float p2x = d2x*i2, p2y = d2y*i2, p2z = d2z*i2;
        float cx = (p1y*p2z - p1z*p2y) * INV_SQRT6;
        float cy = (p1z*p2x - p1x*p2z) * INV_SQRT6;
        float cz = (p1x*p2y - p1y*p2x) * INV_SQRT6;
#pragma unroll
        for (int l = Ss; l < Ll; l++) {
            float4 t1 = g_t1[l * Hh + hg];
            float rxa = p1x * t1.x + p2x * t1.y + cx * t1.z;
            float rya = p1y * t1.x + p2y * t1.y + cy * t1.z;
            float rza = p1z * t1.x + p2z * t1.y + cz * t1.z;
            float4 t0 = g_t0[l * Hh + hg];
            float qw = t0.x, s = t0.y, nwg = t0.z, sc = t0.w;
            float qx = s * rxa, qy = s * rya, qz = s * rza;
            float tw = -qx*p1x - qy*p1y - qz*p1z;
            float tx =  qw*p1x + qy*p1z - qz*p1y;
            float ty =  qw*p1y + qz*p1x - qx*p1z;
            float tz =  qw*p1z + qx*p1y - qy*p1x;
            float vx = -tw*qx + tx*qw - ty*qz + tz*qy;
            float vy = -tw*qy + ty*qw - tz*qx + tx*qz;
            float vz = -tw*qz + tz*qw - tx*qy + ty*qx;
            sg[3*(l-Ss) + 0] = (sc * vx + Px) * nwg;
            sg[3*(l-Ss) + 1] = (sc * vy + Py) * nwg;
            sg[3*(l-Ss) + 2] = (sc * vz + Pz) * nwg;
        }
    }
    __syncthreads();

    const int m = (Hh - h0 < HBLK) ? (Hh - h0) : HBLK;   // active h count

    // rot writeout: coalesced float4 from staging
    {
        const int rb = O_ROT + (b * Hh + h0) * 60;       // mod 4 == 0
        const int nv = (60 * m) >> 2;
        const float4* src = (const float4*)buf;
        float4* dst = (float4*)(out + rb);
        for (int v = tid; v < nv; v += HBLK) dst[v] = src[v];
    }

    // st writeout: float4 reshuffle of sx. st[b,i,h,k] = x[b, 10h+i, k]
    for (int i = 0; i < Ll; i++) {
        const int rb = O_ST + (b * Ll + i) * (Hh * 3) + h0 * 3;
        const int rowf = 3 * m;
        const int head = (4 - (rb & 3)) & 3;
        for (int f = tid; f < head; f += HBLK) {
            int dh = f / 3, k = f - 3 * dh;
            out[rb + f] = sx[30 * dh + 30 + 3*i + k];
        }
        const int nv = (rowf - head) >> 2;
        for (int v = tid; v < nv; v += HBLK) {
            int f0 = head + 4 * v;
            float4 q;
            int d0=(f0+0)/3, d1=(f0+1)/3, d2=(f0+2)/3, d3=(f0+3)/3;
            q.x = sx[30*d0 + 30 + 3*i + (f0+0) - 3*d0];
            q.y = sx[30*d1 + 30 + 3*i + (f0+1) - 3*d1];
            q.z = sx[30*d2 + 30 + 3*i + (f0+2) - 3*d2];
            q.w = sx[30*d3 + 30 + 3*i + (f0+3) - 3*d3];
            *(float4*)(out + rb + f0) = q;
        }
        for (int f = head + 4*nv + tid; f < rowf; f += HBLK) {
            int dh = f / 3, k = f - 3 * dh;
            out[rb + f] = sx[30 * dh + 30 + 3*i + k];
        }
    }
    __syncthreads();

    // rec accumulation into buf[0..3840) (aliased with rot staging):
    // phase 1: even tids STORE their 60 floats (tiles [0,3840) exactly)
    if (active && ((tid & 1) == 0)) {
#pragma unroll
        for (int j = 0; j < 60; j++) buf[30 * tid + j] = r[j];
    }
    __syncthreads();
    // phase 2: odd tids ADD (tid 127 only its first 30: l>=10 belongs to next block)
    if (active && ((tid & 1) == 1)) {
        const int jmax = (tid == HBLK - 1) ? 30 : 60;
        for (int j = 0; j < jmax; j++) buf[30 * tid + j] += r[j];
    }
    if (tid == 0 && h0 > 0) {
#pragma unroll
        for (int j = 0; j < 30; j++) buf[j] += sg[j];
    }
    __syncthreads();

    // rec writeback: coalesced float4 plain stores (exclusive ownership)
    {
        const int gb = (b * Nn + base) * 3;              // O_REC == 0, mod 4 == 0
        int maxf = (Nn - base) * 3;
        if (maxf > ACCF) maxf = ACCF;
        const int nv = maxf >> 2;                        // divisible by 4
        const float4* src = (const float4*)buf;
        float4* dst = (float4*)(out + gb);
        for (int v = tid; v < nv; v += HBLK) dst[v] = src[v];
    }
}

// ---------------------------------------------------------------------------
// k_nw: one block per n, vectorized float4 row writes for nw + contribution
// ---------------------------------------------------------------------------
__device__ __forceinline__ void nw_vals(int h, int ended, int started,
                                        int ha, float wA, float wB,
                                        float& cb, float& nw)
{
    cb = (h >= ended && h < started) ? 1.f : 0.f;
    nw = (h == ha) ? wA : ((h == ha - 1) ? wB : 0.f);
}

__global__ void k_nw(const float* __restrict__ W_enc,
                     float* __restrict__ out)
{
    const int n   = blockIdx.x;
    const int tid = threadIdx.x;
    const int bd  = blockDim.x;

    const int started = (n < Nn - Ll) ? (n / Ss + 1) : Hh;
    const int ended   = (n >= Ll) ? ((n - Ss) / Ss) : 0;
    const int ha = n / Ss, l0 = n % Ss;
    const float inv_rs = 1.f / g_rowsum[n];
    const float wA = (ha < Hh) ? W_enc[(l0 * Hh + ha) * 3] * inv_rs : 0.f;
    const float wB = (ha >= 1) ? W_enc[((l0 + Ss) * Hh + ha - 1) * 3] * inv_rs : 0.f;

    const int bn = O_NW + n * Hh;
    const int bc = O_CB + n * Hh;
    const int head = (4 - (n & 3)) & 3;           // bn,bc ≡ n (mod 4)

    for (int h = tid; h < head; h += bd) {
        float cb, nw; nw_vals(h, ended, started, ha, wA, wB, cb, nw);
        out[bn + h] = nw; out[bc + h] = cb;
    }
    const int nvec = (Hh - head) >> 2;
    float4* vn = (float4*)(out + bn + head);
    float4* vc = (float4*)(out + bc + head);
    for (int v = tid; v < nvec; v += bd) {
        int h = head + 4 * v;
        float4 c4, w4;
        nw_vals(h + 0, ended, started, ha, wA, wB, c4.x, w4.x);
        nw_vals(h + 1, ended, started, ha, wA, wB, c4.y, w4.y);
        nw_vals(h + 2, ended, started, ha, wA, wB, c4.z, w4.z);
        nw_vals(h + 3, ended, started, ha, wA, wB, c4.w, w4.w);
        vn[v] = w4; vc[v] = c4;
    }
    for (int h = head + 4 * nvec + tid; h < Hh; h += bd) {
        float cb, nw; nw_vals(h, ended, started, ha, wA, wB, cb, nw);
        out[bn + h] = nw; out[bc + h] = cb;
    }
}

// ---------------------------------------------------------------------------
extern "C" void kernel_launch(void* const* d_in, const int* in_sizes, int n_in,
                              void* d_out, int out_size)
{
    const float* x       = (const float*)d_in[0];
    const float* W_enc   = (const float*)d_in[1];
    const float* W_dec   = (const float*)d_in[2];
    const float* angles  = (const float*)d_in[3];
    const float* scaling = (const float*)d_in[4];
    float* out = (float*)d_out;

    k_tables<<<(HL + 255) / 256, 256>>>(angles, W_enc, W_dec, scaling);

    dim3 gA((Hh + HBLK - 1) / HBLK, Bb);
    k_encode<<<gA, HBLK>>>(x, W_enc, out);

    k_nw<<<Nn, 256>>>(W_enc, out);
}